// round 1
// baseline (speedup 1.0000x reference)
#include <cuda_runtime.h>
#include <math.h>
#include <stdint.h>

constexpr int NB    = 32;
constexpr int NKV   = 2048;
constexpr int NHID  = 2560;
constexpr int NHEADS= 32;
constexpr int NHD   = 80;
constexpr int NNI   = 10240;
constexpr int NQKV  = 3 * NHID;

// Scratch (allocation-free: device globals)
__device__ __align__(16) float g_x[NB * NHID];        // post-LN activations
__device__ __align__(16) float g_qkv[NB * NQKV];      // qkv (rope applied in place)
__device__ __align__(16) float g_attn[NB * NHID];     // attention output (pre out-proj)
__device__ __align__(16) float g_attn_out[NB * NHID]; // attn @ w_out^T + b_out
__device__ __align__(16) float g_hmlp[NB * NNI];      // gelu(fc1)

// ---------------------------------------------------------------------------
// LayerNorm: one block per batch row
// ---------------------------------------------------------------------------
__global__ __launch_bounds__(256) void ln_kernel(
    const float* __restrict__ hs, const float* __restrict__ gam,
    const float* __restrict__ bet, float* __restrict__ xout)
{
    int b = blockIdx.x;
    const float* row = hs + b * NHID;
    float s = 0.f, s2 = 0.f;
    for (int i = threadIdx.x; i < NHID / 4; i += blockDim.x) {
        float4 v = reinterpret_cast<const float4*>(row)[i];
        s  += v.x + v.y + v.z + v.w;
        s2 += v.x * v.x + v.y * v.y + v.z * v.z + v.w * v.w;
    }
    __shared__ float rs[256], rs2[256];
    rs[threadIdx.x] = s; rs2[threadIdx.x] = s2;
    __syncthreads();
    for (int o = 128; o > 0; o >>= 1) {
        if (threadIdx.x < o) {
            rs[threadIdx.x]  += rs[threadIdx.x + o];
            rs2[threadIdx.x] += rs2[threadIdx.x + o];
        }
        __syncthreads();
    }
    float mu  = rs[0] / NHID;
    float var = rs2[0] / NHID - mu * mu;
    float inv = rsqrtf(var + 1e-5f);
    for (int i = threadIdx.x; i < NHID; i += blockDim.x) {
        xout[b * NHID + i] = (row[i] - mu) * inv * gam[i] + bet[i];
    }
}

// ---------------------------------------------------------------------------
// Skinny GEMM: C[32,N] = X[32,K] @ W[N,K]^T + bias, optional epilogue.
// 256 threads = 8 warps; each warp owns 2 output rows (j); lanes split K.
// EPI: 0 = none, 1 = gelu(tanh), 2 = += add1 + add2 (final output)
// ---------------------------------------------------------------------------
template <int EPI>
__global__ __launch_bounds__(256) void gemm32_kernel(
    const float* __restrict__ X, const float* __restrict__ W,
    const float* __restrict__ bias, float* __restrict__ C,
    int N, int K,
    const float* __restrict__ add1, const float* __restrict__ add2)
{
    __shared__ float red[8][32][33];
    int w    = threadIdx.x >> 5;
    int lane = threadIdx.x & 31;
    int j0   = blockIdx.x * 16 + w * 2;

    float acc[2][32];
#pragma unroll
    for (int jj = 0; jj < 2; jj++)
#pragma unroll
        for (int b = 0; b < 32; b++) acc[jj][b] = 0.f;

    const float4* W0 = reinterpret_cast<const float4*>(W + (size_t)j0 * K);
    const float4* W1 = reinterpret_cast<const float4*>(W + (size_t)(j0 + 1) * K);
    const int K4 = K >> 2;

    for (int k4 = lane; k4 < K4; k4 += 32) {
        float4 w0 = W0[k4];
        float4 w1 = W1[k4];
#pragma unroll
        for (int b = 0; b < 32; b++) {
            float4 x = reinterpret_cast<const float4*>(X + (size_t)b * K)[k4];
            acc[0][b] += w0.x * x.x + w0.y * x.y + w0.z * x.z + w0.w * x.w;
            acc[1][b] += w1.x * x.x + w1.y * x.y + w1.z * x.z + w1.w * x.w;
        }
    }

#pragma unroll
    for (int jj = 0; jj < 2; jj++) {
#pragma unroll
        for (int b = 0; b < 32; b++) red[w][lane][b] = acc[jj][b];
        __syncwarp();
        float s = 0.f;
#pragma unroll
        for (int l = 0; l < 32; l++) s += red[w][l][lane];
        __syncwarp();

        int j = j0 + jj;
        float val = s + bias[j];
        if (EPI == 1) {
            float u = val;
            float t = tanhf(0.7978845608028654f * (u + 0.044715f * u * u * u));
            val = 0.5f * u * (1.f + t);
        } else if (EPI == 2) {
            val += add1[(size_t)lane * N + j] + add2[(size_t)lane * N + j];
        }
        C[(size_t)lane * N + j] = val;  // b = lane
    }
}

// ---------------------------------------------------------------------------
// RoPE in place on q and k within g_qkv. 512 threads: (h, i) = (t/16, t%16)
// ---------------------------------------------------------------------------
__global__ __launch_bounds__(512) void rope_kernel(
    const int* __restrict__ ctxl, float* __restrict__ qkv)
{
    int b = blockIdx.x;
    int t = threadIdx.x;
    int h = t >> 4;
    int i = t & 15;
    float pos = (float)ctxl[b];
    // inv_freq = 10000^(-(2i)/32)
    float inv_freq = expf(-(float)(2 * i) / 32.0f * 9.210340371976184f); // ln(1e4)
    float ang = pos * inv_freq;
    float sn, cs;
    sincosf(ang, &sn, &cs);

    float* q = qkv + (size_t)b * NQKV + h * NHD;
    float x1 = q[i], x2 = q[i + 16];
    q[i]      = x1 * cs - x2 * sn;
    q[i + 16] = x2 * cs + x1 * sn;

    float* k = qkv + (size_t)b * NQKV + NHID + h * NHD;
    x1 = k[i]; x2 = k[i + 16];
    k[i]      = x1 * cs - x2 * sn;
    k[i + 16] = x2 * cs + x1 * sn;
}

// ---------------------------------------------------------------------------
// Flash-decode attention: one block per (head, batch). 256 threads.
// New token k/v (position == ctx) comes from qkv buffer, not the cache.
// ---------------------------------------------------------------------------
__global__ __launch_bounds__(256) void attn_kernel(
    const int* __restrict__ ctxl,
    const float* __restrict__ kc, const float* __restrict__ vc,
    const float* __restrict__ qkv, float* __restrict__ attn)
{
    __shared__ float  sP[NKV];
    __shared__ float4 sQ[20];
    __shared__ float  sRed[256];
    __shared__ float  sAcc[8][80];

    int h = blockIdx.x, b = blockIdx.y;
    int tid = threadIdx.x;
    int ctx = ctxl[b];
    int L = ctx + 1;

    const float* qp = qkv + (size_t)b * NQKV + h * NHD;
    if (tid < 20) sQ[tid] = reinterpret_cast<const float4*>(qp)[tid];
    __syncthreads();

    const float scale = 0.11180339887498948f; // 80^-0.5
    const float* knew = qkv + (size_t)b * NQKV + NHID + h * NHD;
    const float* vnew = qkv + (size_t)b * NQKV + 2 * NHID + h * NHD;

    // Pass 1: scores
    float lmax = -1e30f;
    for (int s = tid; s < L; s += 256) {
        const float* kr = (s == ctx)
            ? knew
            : kc + (((size_t)b * NKV + s) * NHEADS + h) * NHD;
        float d = 0.f;
#pragma unroll
        for (int i = 0; i < 20; i++) {
            float4 k4 = reinterpret_cast<const float4*>(kr)[i];
            float4 q4 = sQ[i];
            d += k4.x * q4.x + k4.y * q4.y + k4.z * q4.z + k4.w * q4.w;
        }
        d *= scale;
        sP[s] = d;
        lmax = fmaxf(lmax, d);
    }
    sRed[tid] = lmax;
    __syncthreads();
    for (int o = 128; o > 0; o >>= 1) {
        if (tid < o) sRed[tid] = fmaxf(sRed[tid], sRed[tid + o]);
        __syncthreads();
    }
    float m = sRed[0];
    __syncthreads();

    float lsum = 0.f;
    for (int s = tid; s < L; s += 256) {
        float e = __expf(sP[s] - m);
        sP[s] = e;
        lsum += e;
    }
    sRed[tid] = lsum;
    __syncthreads();
    for (int o = 128; o > 0; o >>= 1) {
        if (tid < o) sRed[tid] += sRed[tid + o];
        __syncthreads();
    }
    float inv = 1.f / sRed[0];
    __syncthreads();

    // Pass 2: weighted V, warps split s
    int w = tid >> 5, lane = tid & 31;
    float a0 = 0.f, a1 = 0.f, a2 = 0.f;
    for (int s = w; s < L; s += 8) {
        float p = sP[s];
        const float* vr = (s == ctx)
            ? vnew
            : vc + (((size_t)b * NKV + s) * NHEADS + h) * NHD;
        a0 += p * vr[lane];
        a1 += p * vr[lane + 32];
        if (lane < 16) a2 += p * vr[lane + 64];
    }
    sAcc[w][lane]      = a0;
    sAcc[w][lane + 32] = a1;
    if (lane < 16) sAcc[w][lane + 64] = a2;
    __syncthreads();

    if (tid < 80) {
        float s = 0.f;
#pragma unroll
        for (int ww = 0; ww < 8; ww++) s += sAcc[ww][tid];
        attn[(size_t)b * NHID + h * NHD + tid] = s * inv;
    }
}

// ---------------------------------------------------------------------------
extern "C" void kernel_launch(void* const* d_in, const int* in_sizes, int n_in,
                              void* d_out, int out_size)
{
    const float* hs    = (const float*)d_in[0];
    const int*   ctx   = (const int*)  d_in[1];
    const float* kc    = (const float*)d_in[2];
    const float* vc    = (const float*)d_in[3];
    const float* ln_g  = (const float*)d_in[4];
    const float* ln_b  = (const float*)d_in[5];
    const float* w_qkv = (const float*)d_in[6];
    const float* b_qkv = (const float*)d_in[7];
    const float* w_out = (const float*)d_in[8];
    const float* b_out = (const float*)d_in[9];
    const float* w_fc1 = (const float*)d_in[10];
    const float* b_fc1 = (const float*)d_in[11];
    const float* w_fc2 = (const float*)d_in[12];
    const float* b_fc2 = (const float*)d_in[13];
    float* out = (float*)d_out;

    float *px, *pqkv, *pattn, *pao, *ph;
    cudaGetSymbolAddress((void**)&px,    g_x);
    cudaGetSymbolAddress((void**)&pqkv,  g_qkv);
    cudaGetSymbolAddress((void**)&pattn, g_attn);
    cudaGetSymbolAddress((void**)&pao,   g_attn_out);
    cudaGetSymbolAddress((void**)&ph,    g_hmlp);

    // 1. LayerNorm
    ln_kernel<<<NB, 256>>>(hs, ln_g, ln_b, px);
    // 2. QKV projection
    gemm32_kernel<0><<<NQKV / 16, 256>>>(px, w_qkv, b_qkv, pqkv, NQKV, NHID,
                                         nullptr, nullptr);
    // 3. RoPE in place on q, k
    rope_kernel<<<NB, 512>>>(ctx, pqkv);
    // 4. Attention (flash-decode, new token handled inline)
    dim3 ag(NHEADS, NB);
    attn_kernel<<<ag, 256>>>(ctx, kc, vc, pqkv, pattn);
    // 5. Output projection
    gemm32_kernel<0><<<NHID / 16, 256>>>(pattn, w_out, b_out, pao, NHID, NHID,
                                         nullptr, nullptr);
    // 6. MLP fc1 + gelu
    gemm32_kernel<1><<<NNI / 16, 256>>>(px, w_fc1, b_fc1, ph, NNI, NHID,
                                        nullptr, nullptr);
    // 7. MLP fc2 + attn_out + residual -> final output
    gemm32_kernel<2><<<NHID / 16, 256>>>(ph, w_fc2, b_fc2, out, NHID, NNI,
                                         pao, hs);
}

// round 2
// speedup vs baseline: 1.5494x; 1.5494x over previous
#include <cuda_runtime.h>
#include <math.h>
#include <stdint.h>

constexpr int NB    = 32;
constexpr int NKV   = 2048;
constexpr int NHID  = 2560;
constexpr int NHEADS= 32;
constexpr int NHD   = 80;
constexpr int NNI   = 10240;
constexpr int NQKV  = 3 * NHID;
constexpr int KTILE = 160;     // k-tile staged in smem (multiple of 8)
constexpr int ASPLIT= 4;       // attention KV splits

// Scratch (allocation-free: device globals)
__device__ __align__(16) float g_x[NB * NHID];          // post-LN activations
__device__ __align__(16) float g_qkv[NB * NQKV];        // qkv (rope in place)
__device__ __align__(16) float g_attn[NB * NHID];       // attention out (pre out-proj)
__device__ __align__(16) float g_attn_out[NB * NHID];   // attn @ w_out^T + b_out
__device__ __align__(16) float g_hmlp[NB * NNI];        // gelu(fc1)
__device__ __align__(16) float g_part[2 * 1024 * 1024]; // split-K partials (8MB)
__device__ __align__(16) float g_pm[NB * NHEADS * ASPLIT];
__device__ __align__(16) float g_pl[NB * NHEADS * ASPLIT];
__device__ __align__(16) float g_po[NB * NHEADS * ASPLIT * NHD];

// ---------------------------------------------------------------------------
__device__ __forceinline__ uint32_t f2tf32(float x) {
    uint32_t r;
    asm("cvt.rna.tf32.f32 %0, %1;" : "=r"(r) : "f"(x));
    return r;
}

__device__ __forceinline__ void mma_tf32(float* d, const uint32_t* a,
                                         uint32_t b0, uint32_t b1) {
    asm volatile(
        "mma.sync.aligned.m16n8k8.row.col.f32.tf32.tf32.f32 "
        "{%0,%1,%2,%3}, {%4,%5,%6,%7}, {%8,%9}, {%0,%1,%2,%3};\n"
        : "+f"(d[0]), "+f"(d[1]), "+f"(d[2]), "+f"(d[3])
        : "r"(a[0]), "r"(a[1]), "r"(a[2]), "r"(a[3]), "r"(b0), "r"(b1));
}

// ---------------------------------------------------------------------------
// LayerNorm: one block per batch row
// ---------------------------------------------------------------------------
__global__ __launch_bounds__(256) void ln_kernel(
    const float* __restrict__ hs, const float* __restrict__ gam,
    const float* __restrict__ bet, float* __restrict__ xout)
{
    int b = blockIdx.x;
    const float* row = hs + b * NHID;
    float s = 0.f, s2 = 0.f;
    for (int i = threadIdx.x; i < NHID / 4; i += blockDim.x) {
        float4 v = reinterpret_cast<const float4*>(row)[i];
        s  += v.x + v.y + v.z + v.w;
        s2 += v.x * v.x + v.y * v.y + v.z * v.z + v.w * v.w;
    }
    __shared__ float rs[256], rs2[256];
    rs[threadIdx.x] = s; rs2[threadIdx.x] = s2;
    __syncthreads();
    for (int o = 128; o > 0; o >>= 1) {
        if (threadIdx.x < o) {
            rs[threadIdx.x]  += rs[threadIdx.x + o];
            rs2[threadIdx.x] += rs2[threadIdx.x + o];
        }
        __syncthreads();
    }
    float mu  = rs[0] / NHID;
    float var = rs2[0] / NHID - mu * mu;
    float inv = rsqrtf(var + 1e-5f);
    for (int i = threadIdx.x; i < NHID; i += blockDim.x) {
        xout[b * NHID + i] = (row[i] - mu) * inv * gam[i] + bet[i];
    }
}

// ---------------------------------------------------------------------------
// tf32 split-K GEMM: part[ks][32,N] = X[32, Kslice] @ W[N, Kslice]^T
// Block: 256 thr (8 warps). Warp computes a 32(m) x 32(n) tile.
// grid.x = N/256, grid.y = KSPLIT. Kper = K/KSPLIT must be multiple of KTILE.
// ---------------------------------------------------------------------------
__global__ __launch_bounds__(256) void gemm_tf32_kernel(
    const float* __restrict__ X, const float* __restrict__ W,
    float* __restrict__ part, int N, int K, int Kper)
{
    __shared__ uint32_t Xs[32][KTILE + 4];

    int tid  = threadIdx.x;
    int w    = tid >> 5;
    int lane = tid & 31;
    int g    = lane >> 2;   // 0..7
    int t    = lane & 3;    // 0..3

    int nwarp = blockIdx.x * 256 + w * 32;
    int ks    = blockIdx.y * Kper;
    int ke    = ks + Kper;

    float d[2][4][4];
#pragma unroll
    for (int m = 0; m < 2; m++)
#pragma unroll
        for (int nt = 0; nt < 4; nt++)
#pragma unroll
            for (int f = 0; f < 4; f++) d[m][nt][f] = 0.f;

    // per-n-subtile W row pointers at (n, ks + t)
    const float* wp0 = W + (size_t)(nwarp +  0 + g) * K + ks + t;
    const float* wp1 = W + (size_t)(nwarp +  8 + g) * K + ks + t;
    const float* wp2 = W + (size_t)(nwarp + 16 + g) * K + ks + t;
    const float* wp3 = W + (size_t)(nwarp + 24 + g) * K + ks + t;

    for (int kt = ks; kt < ke; kt += KTILE) {
        // stage + tf32-convert X[32, KTILE]
        for (int idx = tid; idx < 32 * (KTILE / 4); idx += 256) {
            int row = idx / (KTILE / 4);
            int c4  = idx % (KTILE / 4);
            float4 v = *reinterpret_cast<const float4*>(X + (size_t)row * K + kt + c4 * 4);
            uint4 u;
            u.x = f2tf32(v.x); u.y = f2tf32(v.y);
            u.z = f2tf32(v.z); u.w = f2tf32(v.w);
            *reinterpret_cast<uint4*>(&Xs[row][c4 * 4]) = u;
        }
        __syncthreads();

        int koff = kt - ks;
#pragma unroll 4
        for (int k8 = 0; k8 < KTILE; k8 += 8) {
            uint32_t a0[4], a1[4];
            a0[0] = Xs[g     ][k8 + t];
            a0[1] = Xs[g +  8][k8 + t];
            a0[2] = Xs[g     ][k8 + t + 4];
            a0[3] = Xs[g +  8][k8 + t + 4];
            a1[0] = Xs[g + 16][k8 + t];
            a1[1] = Xs[g + 24][k8 + t];
            a1[2] = Xs[g + 16][k8 + t + 4];
            a1[3] = Xs[g + 24][k8 + t + 4];

            int kk = koff + k8;
            uint32_t b00 = f2tf32(wp0[kk]), b01 = f2tf32(wp0[kk + 4]);
            uint32_t b10 = f2tf32(wp1[kk]), b11 = f2tf32(wp1[kk + 4]);
            uint32_t b20 = f2tf32(wp2[kk]), b21 = f2tf32(wp2[kk + 4]);
            uint32_t b30 = f2tf32(wp3[kk]), b31 = f2tf32(wp3[kk + 4]);

            mma_tf32(d[0][0], a0, b00, b01);
            mma_tf32(d[1][0], a1, b00, b01);
            mma_tf32(d[0][1], a0, b10, b11);
            mma_tf32(d[1][1], a1, b10, b11);
            mma_tf32(d[0][2], a0, b20, b21);
            mma_tf32(d[1][2], a1, b20, b21);
            mma_tf32(d[0][3], a0, b30, b31);
            mma_tf32(d[1][3], a1, b30, b31);
        }
        __syncthreads();
    }

    // write partials: part[(gy*32 + row) * N + col]
    float* pbase = part + (size_t)blockIdx.y * 32 * N;
#pragma unroll
    for (int m = 0; m < 2; m++) {
#pragma unroll
        for (int nt = 0; nt < 4; nt++) {
            int col = nwarp + nt * 8 + 2 * t;
            int r0  = g + m * 16;
            float2 lo = make_float2(d[m][nt][0], d[m][nt][1]);
            float2 hi = make_float2(d[m][nt][2], d[m][nt][3]);
            *reinterpret_cast<float2*>(pbase + (size_t)r0 * N + col)       = lo;
            *reinterpret_cast<float2*>(pbase + (size_t)(r0 + 8) * N + col) = hi;
        }
    }
}

// ---------------------------------------------------------------------------
// split-K reduce + bias + epilogue. One thread per output element.
// EPI: 0 = bias only, 1 = gelu(tanh), 2 = += add1 + add2 (final)
// ---------------------------------------------------------------------------
template <int EPI>
__global__ __launch_bounds__(256) void reduce_kernel(
    const float* __restrict__ part, const float* __restrict__ bias,
    float* __restrict__ C, int N, int KS,
    const float* __restrict__ add1, const float* __restrict__ add2)
{
    int id = blockIdx.x * 256 + threadIdx.x;
    if (id >= 32 * N) return;
    int j = id % N;
    float s = 0.f;
    for (int z = 0; z < KS; z++) s += part[(size_t)z * 32 * N + id];
    float val = s + bias[j];
    if (EPI == 1) {
        float u = val;
        float th = tanhf(0.7978845608028654f * (u + 0.044715f * u * u * u));
        val = 0.5f * u * (1.f + th);
    } else if (EPI == 2) {
        val += add1[id] + add2[id];
    }
    C[id] = val;
}

// ---------------------------------------------------------------------------
// RoPE in place on q and k within g_qkv. 512 threads: (h, i) = (t/16, t%16)
// ---------------------------------------------------------------------------
__global__ __launch_bounds__(512) void rope_kernel(
    const int* __restrict__ ctxl, float* __restrict__ qkv)
{
    int b = blockIdx.x;
    int t = threadIdx.x;
    int h = t >> 4;
    int i = t & 15;
    float pos = (float)ctxl[b];
    float inv_freq = expf(-(float)(2 * i) / 32.0f * 9.210340371976184f);
    float ang = pos * inv_freq;
    float sn, cs;
    sincosf(ang, &sn, &cs);

    float* q = qkv + (size_t)b * NQKV + h * NHD;
    float x1 = q[i], x2 = q[i + 16];
    q[i]      = x1 * cs - x2 * sn;
    q[i + 16] = x2 * cs + x1 * sn;

    float* k = qkv + (size_t)b * NQKV + NHID + h * NHD;
    x1 = k[i]; x2 = k[i + 16];
    k[i]      = x1 * cs - x2 * sn;
    k[i + 16] = x2 * cs + x1 * sn;
}

// ---------------------------------------------------------------------------
// Flash-decode attention, split-KV: one block per (head, batch, split).
// Writes unnormalized partials (m, l, o) for later combine.
// ---------------------------------------------------------------------------
__global__ __launch_bounds__(256) void attn_split_kernel(
    const int* __restrict__ ctxl,
    const float* __restrict__ kc, const float* __restrict__ vc,
    const float* __restrict__ qkv,
    float* __restrict__ pm, float* __restrict__ pl, float* __restrict__ po)
{
    __shared__ float  sP[512];
    __shared__ float4 sQ[20];
    __shared__ float  sRed[256];
    __shared__ float  sAcc[8][80];

    int h = blockIdx.x, b = blockIdx.y, z = blockIdx.z;
    int tid = threadIdx.x;
    int ctx = ctxl[b];
    int L = ctx + 1;
    int s0 = z * 512;
    int s1 = min(L, s0 + 512);
    int pidx = ((b * NHEADS + h) * ASPLIT + z);

    if (s0 >= L) {
        if (tid == 0) { pm[pidx] = -1e30f; pl[pidx] = 0.f; }
        if (tid < NHD) po[(size_t)pidx * NHD + tid] = 0.f;
        return;
    }

    const float* qp = qkv + (size_t)b * NQKV + h * NHD;
    if (tid < 20) sQ[tid] = reinterpret_cast<const float4*>(qp)[tid];
    __syncthreads();

    const float scale = 0.11180339887498948f; // 80^-0.5
    const float* knew = qkv + (size_t)b * NQKV + NHID + h * NHD;
    const float* vnew = qkv + (size_t)b * NQKV + 2 * NHID + h * NHD;

    // Pass 1: scores
    float lmax = -1e30f;
    for (int s = s0 + tid; s < s1; s += 256) {
        const float* kr = (s == ctx)
            ? knew
            : kc + (((size_t)b * NKV + s) * NHEADS + h) * NHD;
        float dsc = 0.f;
#pragma unroll
        for (int i = 0; i < 20; i++) {
            float4 k4 = reinterpret_cast<const float4*>(kr)[i];
            float4 q4 = sQ[i];
            dsc += k4.x * q4.x + k4.y * q4.y + k4.z * q4.z + k4.w * q4.w;
        }
        dsc *= scale;
        sP[s - s0] = dsc;
        lmax = fmaxf(lmax, dsc);
    }
    sRed[tid] = lmax;
    __syncthreads();
    for (int o = 128; o > 0; o >>= 1) {
        if (tid < o) sRed[tid] = fmaxf(sRed[tid], sRed[tid + o]);
        __syncthreads();
    }
    float m = sRed[0];
    __syncthreads();

    float lsum = 0.f;
    for (int s = s0 + tid; s < s1; s += 256) {
        float e = __expf(sP[s - s0] - m);
        sP[s - s0] = e;
        lsum += e;
    }
    sRed[tid] = lsum;
    __syncthreads();
    for (int o = 128; o > 0; o >>= 1) {
        if (tid < o) sRed[tid] += sRed[tid + o];
        __syncthreads();
    }
    float l = sRed[0];
    __syncthreads();

    // Pass 2: weighted V (unnormalized), warps split s
    int w = tid >> 5, lane = tid & 31;
    float a0 = 0.f, a1 = 0.f, a2 = 0.f;
    for (int s = s0 + w; s < s1; s += 8) {
        float p = sP[s - s0];
        const float* vr = (s == ctx)
            ? vnew
            : vc + (((size_t)b * NKV + s) * NHEADS + h) * NHD;
        a0 += p * vr[lane];
        a1 += p * vr[lane + 32];
        if (lane < 16) a2 += p * vr[lane + 64];
    }
    sAcc[w][lane]      = a0;
    sAcc[w][lane + 32] = a1;
    if (lane < 16) sAcc[w][lane + 64] = a2;
    __syncthreads();

    if (tid < NHD) {
        float s = 0.f;
#pragma unroll
        for (int ww = 0; ww < 8; ww++) s += sAcc[ww][tid];
        po[(size_t)pidx * NHD + tid] = s;
    }
    if (tid == 0) { pm[pidx] = m; pl[pidx] = l; }
}

// ---------------------------------------------------------------------------
// Combine attention partials
// ---------------------------------------------------------------------------
__global__ __launch_bounds__(128) void attn_combine_kernel(
    const float* __restrict__ pm, const float* __restrict__ pl,
    const float* __restrict__ po, float* __restrict__ attn)
{
    int h = blockIdx.x, b = blockIdx.y;
    int tid = threadIdx.x;
    if (tid >= NHD) return;
    int base = (b * NHEADS + h) * ASPLIT;

    float M = -1e30f;
#pragma unroll
    for (int z = 0; z < ASPLIT; z++) M = fmaxf(M, pm[base + z]);
    float den = 0.f, num = 0.f;
#pragma unroll
    for (int z = 0; z < ASPLIT; z++) {
        float wz = __expf(pm[base + z] - M);
        den += wz * pl[base + z];
        num += wz * po[(size_t)(base + z) * NHD + tid];
    }
    attn[(size_t)b * NHID + h * NHD + tid] = num / den;
}

// ---------------------------------------------------------------------------
extern "C" void kernel_launch(void* const* d_in, const int* in_sizes, int n_in,
                              void* d_out, int out_size)
{
    const float* hs    = (const float*)d_in[0];
    const int*   ctx   = (const int*)  d_in[1];
    const float* kc    = (const float*)d_in[2];
    const float* vc    = (const float*)d_in[3];
    const float* ln_g  = (const float*)d_in[4];
    const float* ln_b  = (const float*)d_in[5];
    const float* w_qkv = (const float*)d_in[6];
    const float* b_qkv = (const float*)d_in[7];
    const float* w_out = (const float*)d_in[8];
    const float* b_out = (const float*)d_in[9];
    const float* w_fc1 = (const float*)d_in[10];
    const float* b_fc1 = (const float*)d_in[11];
    const float* w_fc2 = (const float*)d_in[12];
    const float* b_fc2 = (const float*)d_in[13];
    float* out = (float*)d_out;

    float *px, *pqkv, *pattn, *pao, *ph, *ppart, *ppm, *ppl, *ppo;
    cudaGetSymbolAddress((void**)&px,    g_x);
    cudaGetSymbolAddress((void**)&pqkv,  g_qkv);
    cudaGetSymbolAddress((void**)&pattn, g_attn);
    cudaGetSymbolAddress((void**)&pao,   g_attn_out);
    cudaGetSymbolAddress((void**)&ph,    g_hmlp);
    cudaGetSymbolAddress((void**)&ppart, g_part);
    cudaGetSymbolAddress((void**)&ppm,   g_pm);
    cudaGetSymbolAddress((void**)&ppl,   g_pl);
    cudaGetSymbolAddress((void**)&ppo,   g_po);

    // 1. LayerNorm
    ln_kernel<<<NB, 256>>>(hs, ln_g, ln_b, px);

    // 2. QKV projection (N=7680, K=2560, KS=8 -> Kper=320)
    {
        dim3 gr(NQKV / 256, 8);
        gemm_tf32_kernel<<<gr, 256>>>(px, w_qkv, ppart, NQKV, NHID, NHID / 8);
        reduce_kernel<0><<<(32 * NQKV + 255) / 256, 256>>>(ppart, b_qkv, pqkv,
                                                           NQKV, 8, nullptr, nullptr);
    }

    // 3. RoPE in place on q, k
    rope_kernel<<<NB, 512>>>(ctx, pqkv);

    // 4. Attention (split flash-decode + combine)
    {
        dim3 ag(NHEADS, NB, ASPLIT);
        attn_split_kernel<<<ag, 256>>>(ctx, kc, vc, pqkv, ppm, ppl, ppo);
        dim3 cg(NHEADS, NB);
        attn_combine_kernel<<<cg, 128>>>(ppm, ppl, ppo, pattn);
    }

    // 5. Output projection (N=2560, K=2560, KS=16 -> Kper=160)
    {
        dim3 gr(NHID / 256, 16);
        gemm_tf32_kernel<<<gr, 256>>>(pattn, w_out, ppart, NHID, NHID, NHID / 16);
        reduce_kernel<0><<<(32 * NHID + 255) / 256, 256>>>(ppart, b_out, pao,
                                                           NHID, 16, nullptr, nullptr);
    }

    // 6. MLP fc1 + gelu (N=10240, K=2560, KS=4 -> Kper=640)
    {
        dim3 gr(NNI / 256, 4);
        gemm_tf32_kernel<<<gr, 256>>>(px, w_fc1, ppart, NNI, NHID, NHID / 4);
        reduce_kernel<1><<<(32 * NNI + 255) / 256, 256>>>(ppart, b_fc1, ph,
                                                          NNI, 4, nullptr, nullptr);
    }

    // 7. MLP fc2 + attn_out + residual (N=2560, K=10240, KS=16 -> Kper=640)
    {
        dim3 gr(NHID / 256, 16);
        gemm_tf32_kernel<<<gr, 256>>>(ph, w_fc2, ppart, NHID, NNI, NNI / 16);
        reduce_kernel<2><<<(32 * NHID + 255) / 256, 256>>>(ppart, b_fc2, out,
                                                           NHID, 16, pao, hs);
    }
}

// round 3
// speedup vs baseline: 1.8608x; 1.2010x over previous
#include <cuda_runtime.h>
#include <math.h>
#include <stdint.h>

constexpr int NB    = 32;
constexpr int NKV   = 2048;
constexpr int NHID  = 2560;
constexpr int NHEADS= 32;
constexpr int NHD   = 80;
constexpr int NNI   = 10240;
constexpr int NQKV  = 3 * NHID;
constexpr int ASPLIT= 8;       // attention KV splits
constexpr int ATOK  = 256;     // tokens per attention block

// GEMM tiling
constexpr int GK  = 64;        // k-tile
constexpr int GN  = 128;       // n per block (4 warps x 32)
constexpr int XS_STRIDE = 68;  // 272B rows: 16B aligned, conflict-free frags
constexpr int WS_STRIDE = 64;  // swizzled
constexpr int XS_FLOATS = 32 * XS_STRIDE;          // 2176
constexpr int WS_FLOATS = GN * WS_STRIDE;          // 8192
constexpr int SMEM_FLOATS = 2 * (XS_FLOATS + WS_FLOATS);
constexpr int SMEM_BYTES  = SMEM_FLOATS * 4;       // 82944

// Scratch (allocation-free: device globals)
__device__ __align__(16) float g_x[NB * NHID];
__device__ __align__(16) float g_qkv[NB * NQKV];
__device__ __align__(16) float g_attn[NB * NHID];
__device__ __align__(16) float g_attn_out[NB * NHID];
__device__ __align__(16) float g_hmlp[NB * NNI];
__device__ __align__(16) float g_part[2 * 1024 * 1024];
__device__ __align__(16) float g_pm[NB * NHEADS * ASPLIT];
__device__ __align__(16) float g_pl[NB * NHEADS * ASPLIT];
__device__ __align__(16) float g_po[NB * NHEADS * ASPLIT * NHD];

// ---------------------------------------------------------------------------
__device__ __forceinline__ uint32_t f2tf32(float x) {
    uint32_t r;
    asm("cvt.rna.tf32.f32 %0, %1;" : "=r"(r) : "f"(x));
    return r;
}

__device__ __forceinline__ void mma_tf32(float* d, const uint32_t* a,
                                         uint32_t b0, uint32_t b1) {
    asm volatile(
        "mma.sync.aligned.m16n8k8.row.col.f32.tf32.tf32.f32 "
        "{%0,%1,%2,%3}, {%4,%5,%6,%7}, {%8,%9}, {%0,%1,%2,%3};\n"
        : "+f"(d[0]), "+f"(d[1]), "+f"(d[2]), "+f"(d[3])
        : "r"(a[0]), "r"(a[1]), "r"(a[2]), "r"(a[3]), "r"(b0), "r"(b1));
}

__device__ __forceinline__ void cp_async16(void* dst, const void* src) {
    uint32_t s = (uint32_t)__cvta_generic_to_shared(dst);
    asm volatile("cp.async.cg.shared.global [%0], [%1], 16;\n"
                 :: "r"(s), "l"(src));
}

// ---------------------------------------------------------------------------
// LayerNorm: one block per batch row
// ---------------------------------------------------------------------------
__global__ __launch_bounds__(256) void ln_kernel(
    const float* __restrict__ hs, const float* __restrict__ gam,
    const float* __restrict__ bet, float* __restrict__ xout)
{
    int b = blockIdx.x;
    const float* row = hs + b * NHID;
    float s = 0.f, s2 = 0.f;
    for (int i = threadIdx.x; i < NHID / 4; i += blockDim.x) {
        float4 v = reinterpret_cast<const float4*>(row)[i];
        s  += v.x + v.y + v.z + v.w;
        s2 += v.x * v.x + v.y * v.y + v.z * v.z + v.w * v.w;
    }
    __shared__ float rs[256], rs2[256];
    rs[threadIdx.x] = s; rs2[threadIdx.x] = s2;
    __syncthreads();
    for (int o = 128; o > 0; o >>= 1) {
        if (threadIdx.x < o) {
            rs[threadIdx.x]  += rs[threadIdx.x + o];
            rs2[threadIdx.x] += rs2[threadIdx.x + o];
        }
        __syncthreads();
    }
    float mu  = rs[0] / NHID;
    float var = rs2[0] / NHID - mu * mu;
    float inv = rsqrtf(var + 1e-5f);
    for (int i = threadIdx.x; i < NHID; i += blockDim.x) {
        xout[b * NHID + i] = (row[i] - mu) * inv * gam[i] + bet[i];
    }
}

// ---------------------------------------------------------------------------
// tf32 split-K GEMM, cp.async double-buffered:
//   part[ky][32, N] += X[32, Kslice] @ W[N, Kslice]^T
// Block: 128 thr (4 warps). Warp computes 32(m) x 32(n). Block tile n=128.
// grid.x = N/128, grid.y = KSPLIT. Kper % 64 == 0.
// W smem rows are XOR-swizzled: phys_col = col ^ ((row & 7) << 2)
// ---------------------------------------------------------------------------
__global__ __launch_bounds__(128) void gemm_tf32_kernel(
    const float* __restrict__ X, const float* __restrict__ W,
    float* __restrict__ part, int N, int K, int Kper)
{
    extern __shared__ float sm[];
    float* XsBuf[2] = { sm, sm + XS_FLOATS };
    float* WsBuf[2] = { sm + 2 * XS_FLOATS, sm + 2 * XS_FLOATS + WS_FLOATS };

    int tid  = threadIdx.x;
    int w    = tid >> 5;
    int lane = tid & 31;
    int g    = lane >> 2;   // 0..7
    int t    = lane & 3;    // 0..3

    int nbase  = blockIdx.x * GN;
    int nwarp  = nbase + w * 32;
    int ks     = blockIdx.y * Kper;
    int ntiles = Kper / GK;

    // staging identities (2048 W chunks, 512 X chunks of 16B)
    int wrow = tid >> 2;          // X staging row helper below
    (void)wrow;

    float d[2][4][4];
#pragma unroll
    for (int m = 0; m < 2; m++)
#pragma unroll
        for (int s = 0; s < 4; s++)
#pragma unroll
            for (int f = 0; f < 4; f++) d[m][s][f] = 0.f;

    // --- staging lambdas ---
    auto stageW = [&](int st, int kt) {
        float* ws = WsBuf[st];
#pragma unroll
        for (int i = 0; i < 16; i++) {
            int c   = tid + i * 128;      // 0..2047
            int row = c >> 4;             // 0..127
            int cc  = (c & 15) * 4;       // col (floats)
            int pc  = cc ^ ((row & 7) << 2);
            cp_async16(ws + row * WS_STRIDE + pc,
                       W + (size_t)(nbase + row) * K + kt + cc);
        }
        asm volatile("cp.async.commit_group;\n");
    };
    float4 xr[4];
    auto loadX = [&](int kt) {
#pragma unroll
        for (int i = 0; i < 4; i++) {
            int c   = tid + i * 128;      // 0..511
            int row = c >> 4;             // 0..31
            int cc  = (c & 15) * 4;
            xr[i] = *reinterpret_cast<const float4*>(X + (size_t)row * K + kt + cc);
        }
    };
    auto storeX = [&](int st) {
        float* xs = XsBuf[st];
#pragma unroll
        for (int i = 0; i < 4; i++) {
            int c   = tid + i * 128;
            int row = c >> 4;
            int cc  = (c & 15) * 4;
            uint4 u;
            u.x = f2tf32(xr[i].x); u.y = f2tf32(xr[i].y);
            u.z = f2tf32(xr[i].z); u.w = f2tf32(xr[i].w);
            *reinterpret_cast<uint4*>(xs + row * XS_STRIDE + cc) = u;
        }
    };

    // prologue
    stageW(0, ks);
    loadX(ks);
    storeX(0);
    asm volatile("cp.async.wait_group 0;\n");
    __syncthreads();

    for (int it = 0; it < ntiles; it++) {
        int cur = it & 1;
        bool more = (it + 1 < ntiles);
        if (more) {
            stageW(cur ^ 1, ks + (it + 1) * GK);
            loadX(ks + (it + 1) * GK);
        }

        const uint32_t* xs = reinterpret_cast<const uint32_t*>(XsBuf[cur]);
        const float*    ws = WsBuf[cur];
        int sw = (g << 2);  // W row swizzle for rows with (row&7)==g
#pragma unroll
        for (int k8 = 0; k8 < GK; k8 += 8) {
            uint32_t a0[4], a1[4];
            a0[0] = xs[(g     ) * XS_STRIDE + k8 + t];
            a0[1] = xs[(g +  8) * XS_STRIDE + k8 + t];
            a0[2] = xs[(g     ) * XS_STRIDE + k8 + t + 4];
            a0[3] = xs[(g +  8) * XS_STRIDE + k8 + t + 4];
            a1[0] = xs[(g + 16) * XS_STRIDE + k8 + t];
            a1[1] = xs[(g + 24) * XS_STRIDE + k8 + t];
            a1[2] = xs[(g + 16) * XS_STRIDE + k8 + t + 4];
            a1[3] = xs[(g + 24) * XS_STRIDE + k8 + t + 4];
#pragma unroll
            for (int s = 0; s < 4; s++) {
                int row = w * 32 + s * 8 + g;       // (row & 7) == g
                uint32_t b0 = f2tf32(ws[row * WS_STRIDE + ((k8 + t    ) ^ sw)]);
                uint32_t b1 = f2tf32(ws[row * WS_STRIDE + ((k8 + t + 4) ^ sw)]);
                mma_tf32(d[0][s], a0, b0, b1);
                mma_tf32(d[1][s], a1, b0, b1);
            }
        }

        if (more) {
            storeX(cur ^ 1);
            asm volatile("cp.async.wait_group 0;\n");
        }
        __syncthreads();
    }

    // write partials
    float* pbase = part + (size_t)blockIdx.y * 32 * N;
#pragma unroll
    for (int m = 0; m < 2; m++) {
#pragma unroll
        for (int s = 0; s < 4; s++) {
            int col = nwarp + s * 8 + 2 * t;
            int r0  = g + m * 16;
            float2 lo = make_float2(d[m][s][0], d[m][s][1]);
            float2 hi = make_float2(d[m][s][2], d[m][s][3]);
            *reinterpret_cast<float2*>(pbase + (size_t)r0 * N + col)       = lo;
            *reinterpret_cast<float2*>(pbase + (size_t)(r0 + 8) * N + col) = hi;
        }
    }
}

// ---------------------------------------------------------------------------
// split-K reduce + bias + epilogue.
// EPI: 0 = bias only, 1 = gelu(tanh), 2 = += add1 + add2 (final)
// ---------------------------------------------------------------------------
template <int EPI>
__global__ __launch_bounds__(256) void reduce_kernel(
    const float* __restrict__ part, const float* __restrict__ bias,
    float* __restrict__ C, int N, int KS,
    const float* __restrict__ add1, const float* __restrict__ add2)
{
    int id = blockIdx.x * 256 + threadIdx.x;
    if (id >= 32 * N) return;
    int j = id % N;
    float s = 0.f;
    for (int z = 0; z < KS; z++) s += part[(size_t)z * 32 * N + id];
    float val = s + bias[j];
    if (EPI == 1) {
        float u = val;
        float th = tanhf(0.7978845608028654f * (u + 0.044715f * u * u * u));
        val = 0.5f * u * (1.f + th);
    } else if (EPI == 2) {
        val += add1[id] + add2[id];
    }
    C[id] = val;
}

// ---------------------------------------------------------------------------
// RoPE in place on q and k within g_qkv.
// ---------------------------------------------------------------------------
__global__ __launch_bounds__(512) void rope_kernel(
    const int* __restrict__ ctxl, float* __restrict__ qkv)
{
    int b = blockIdx.x;
    int t = threadIdx.x;
    int h = t >> 4;
    int i = t & 15;
    float pos = (float)ctxl[b];
    float inv_freq = expf(-(float)(2 * i) / 32.0f * 9.210340371976184f);
    float ang = pos * inv_freq;
    float sn, cs;
    sincosf(ang, &sn, &cs);

    float* q = qkv + (size_t)b * NQKV + h * NHD;
    float x1 = q[i], x2 = q[i + 16];
    q[i]      = x1 * cs - x2 * sn;
    q[i + 16] = x2 * cs + x1 * sn;

    float* k = qkv + (size_t)b * NQKV + NHID + h * NHD;
    x1 = k[i]; x2 = k[i + 16];
    k[i]      = x1 * cs - x2 * sn;
    k[i + 16] = x2 * cs + x1 * sn;
}

// ---------------------------------------------------------------------------
// Flash-decode attention, split-KV: one block per (head, batch, split).
// ---------------------------------------------------------------------------
__global__ __launch_bounds__(256, 4) void attn_split_kernel(
    const int* __restrict__ ctxl,
    const float* __restrict__ kc, const float* __restrict__ vc,
    const float* __restrict__ qkv,
    float* __restrict__ pm, float* __restrict__ pl, float* __restrict__ po)
{
    __shared__ float  sP[ATOK];
    __shared__ float4 sQ[20];
    __shared__ float  sRed[256];
    __shared__ float  sAcc[8][80];

    int h = blockIdx.x, b = blockIdx.y, z = blockIdx.z;
    int tid = threadIdx.x;
    int ctx = ctxl[b];
    int L = ctx + 1;
    int s0 = z * ATOK;
    int s1 = min(L, s0 + ATOK);
    int pidx = ((b * NHEADS + h) * ASPLIT + z);

    if (s0 >= L) {
        if (tid == 0) { pm[pidx] = -1e30f; pl[pidx] = 0.f; }
        if (tid < NHD) po[(size_t)pidx * NHD + tid] = 0.f;
        return;
    }

    const float* qp = qkv + (size_t)b * NQKV + h * NHD;
    if (tid < 20) sQ[tid] = reinterpret_cast<const float4*>(qp)[tid];
    __syncthreads();

    const float scale = 0.11180339887498948f; // 80^-0.5
    const float* knew = qkv + (size_t)b * NQKV + NHID + h * NHD;
    const float* vnew = qkv + (size_t)b * NQKV + 2 * NHID + h * NHD;

    // Pass 1: scores
    float lmax = -1e30f;
    for (int s = s0 + tid; s < s1; s += 256) {
        const float* kr = (s == ctx)
            ? knew
            : kc + (((size_t)b * NKV + s) * NHEADS + h) * NHD;
        float dsc = 0.f;
#pragma unroll
        for (int i = 0; i < 20; i++) {
            float4 k4 = reinterpret_cast<const float4*>(kr)[i];
            float4 q4 = sQ[i];
            dsc += k4.x * q4.x + k4.y * q4.y + k4.z * q4.z + k4.w * q4.w;
        }
        dsc *= scale;
        sP[s - s0] = dsc;
        lmax = fmaxf(lmax, dsc);
    }
    sRed[tid] = lmax;
    __syncthreads();
    for (int o = 128; o > 0; o >>= 1) {
        if (tid < o) sRed[tid] = fmaxf(sRed[tid], sRed[tid + o]);
        __syncthreads();
    }
    float m = sRed[0];
    __syncthreads();

    float lsum = 0.f;
    for (int s = s0 + tid; s < s1; s += 256) {
        float e = __expf(sP[s - s0] - m);
        sP[s - s0] = e;
        lsum += e;
    }
    sRed[tid] = lsum;
    __syncthreads();
    for (int o = 128; o > 0; o >>= 1) {
        if (tid < o) sRed[tid] += sRed[tid + o];
        __syncthreads();
    }
    float l = sRed[0];
    __syncthreads();

    // Pass 2: weighted V (unnormalized), warps split s
    int w = tid >> 5, lane = tid & 31;
    float a0 = 0.f, a1 = 0.f, a2 = 0.f;
    for (int s = s0 + w; s < s1; s += 8) {
        float p = sP[s - s0];
        const float* vr = (s == ctx)
            ? vnew
            : vc + (((size_t)b * NKV + s) * NHEADS + h) * NHD;
        a0 += p * vr[lane];
        a1 += p * vr[lane + 32];
        if (lane < 16) a2 += p * vr[lane + 64];
    }
    sAcc[w][lane]      = a0;
    sAcc[w][lane + 32] = a1;
    if (lane < 16) sAcc[w][lane + 64] = a2;
    __syncthreads();

    if (tid < NHD) {
        float s = 0.f;
#pragma unroll
        for (int ww = 0; ww < 8; ww++) s += sAcc[ww][tid];
        po[(size_t)pidx * NHD + tid] = s;
    }
    if (tid == 0) { pm[pidx] = m; pl[pidx] = l; }
}

// ---------------------------------------------------------------------------
// Combine attention partials
// ---------------------------------------------------------------------------
__global__ __launch_bounds__(128) void attn_combine_kernel(
    const float* __restrict__ pm, const float* __restrict__ pl,
    const float* __restrict__ po, float* __restrict__ attn)
{
    int h = blockIdx.x, b = blockIdx.y;
    int tid = threadIdx.x;
    if (tid >= NHD) return;
    int base = (b * NHEADS + h) * ASPLIT;

    float M = -1e30f;
#pragma unroll
    for (int z = 0; z < ASPLIT; z++) M = fmaxf(M, pm[base + z]);
    float den = 0.f, num = 0.f;
#pragma unroll
    for (int z = 0; z < ASPLIT; z++) {
        float wz = __expf(pm[base + z] - M);
        den += wz * pl[base + z];
        num += wz * po[(size_t)(base + z) * NHD + tid];
    }
    attn[(size_t)b * NHID + h * NHD + tid] = num / den;
}

// ---------------------------------------------------------------------------
extern "C" void kernel_launch(void* const* d_in, const int* in_sizes, int n_in,
                              void* d_out, int out_size)
{
    const float* hs    = (const float*)d_in[0];
    const int*   ctx   = (const int*)  d_in[1];
    const float* kc    = (const float*)d_in[2];
    const float* vc    = (const float*)d_in[3];
    const float* ln_g  = (const float*)d_in[4];
    const float* ln_b  = (const float*)d_in[5];
    const float* w_qkv = (const float*)d_in[6];
    const float* b_qkv = (const float*)d_in[7];
    const float* w_out = (const float*)d_in[8];
    const float* b_out = (const float*)d_in[9];
    const float* w_fc1 = (const float*)d_in[10];
    const float* b_fc1 = (const float*)d_in[11];
    const float* w_fc2 = (const float*)d_in[12];
    const float* b_fc2 = (const float*)d_in[13];
    float* out = (float*)d_out;

    float *px, *pqkv, *pattn, *pao, *ph, *ppart, *ppm, *ppl, *ppo;
    cudaGetSymbolAddress((void**)&px,    g_x);
    cudaGetSymbolAddress((void**)&pqkv,  g_qkv);
    cudaGetSymbolAddress((void**)&pattn, g_attn);
    cudaGetSymbolAddress((void**)&pao,   g_attn_out);
    cudaGetSymbolAddress((void**)&ph,    g_hmlp);
    cudaGetSymbolAddress((void**)&ppart, g_part);
    cudaGetSymbolAddress((void**)&ppm,   g_pm);
    cudaGetSymbolAddress((void**)&ppl,   g_pl);
    cudaGetSymbolAddress((void**)&ppo,   g_po);

    cudaFuncSetAttribute(gemm_tf32_kernel,
                         cudaFuncAttributeMaxDynamicSharedMemorySize, SMEM_BYTES);

    // 1. LayerNorm
    ln_kernel<<<NB, 256>>>(hs, ln_g, ln_b, px);

    // 2. QKV projection (N=7680, K=2560, KS=5 -> Kper=512, grid 300)
    {
        dim3 gr(NQKV / GN, 5);
        gemm_tf32_kernel<<<gr, 128, SMEM_BYTES>>>(px, w_qkv, ppart, NQKV, NHID, 512);
        reduce_kernel<0><<<(32 * NQKV + 255) / 256, 256>>>(ppart, b_qkv, pqkv,
                                                           NQKV, 5, nullptr, nullptr);
    }

    // 3. RoPE in place on q, k
    rope_kernel<<<NB, 512>>>(ctx, pqkv);

    // 4. Attention (split flash-decode + combine)
    {
        dim3 ag(NHEADS, NB, ASPLIT);
        attn_split_kernel<<<ag, 256>>>(ctx, kc, vc, pqkv, ppm, ppl, ppo);
        dim3 cg(NHEADS, NB);
        attn_combine_kernel<<<cg, 128>>>(ppm, ppl, ppo, pattn);
    }

    // 5. Output projection (N=2560, K=2560, KS=10 -> Kper=256, grid 200)
    {
        dim3 gr(NHID / GN, 10);
        gemm_tf32_kernel<<<gr, 128, SMEM_BYTES>>>(pattn, w_out, ppart, NHID, NHID, 256);
        reduce_kernel<0><<<(32 * NHID + 255) / 256, 256>>>(ppart, b_out, pao,
                                                           NHID, 10, nullptr, nullptr);
    }

    // 6. MLP fc1 + gelu (N=10240, K=2560, KS=4 -> Kper=640, grid 320)
    {
        dim3 gr(NNI / GN, 4);
        gemm_tf32_kernel<<<gr, 128, SMEM_BYTES>>>(px, w_fc1, ppart, NNI, NHID, 640);
        reduce_kernel<1><<<(32 * NNI + 255) / 256, 256>>>(ppart, b_fc1, ph,
                                                          NNI, 4, nullptr, nullptr);
    }

    // 7. MLP fc2 + attn_out + residual (N=2560, K=10240, KS=16 -> Kper=640, grid 320)
    {
        dim3 gr(NHID / GN, 16);
        gemm_tf32_kernel<<<gr, 128, SMEM_BYTES>>>(ph, w_fc2, ppart, NHID, NNI, 640);
        reduce_kernel<2><<<(32 * NHID + 255) / 256, 256>>>(ppart, b_fc2, out,
                                                           NHID, 16, pao, hs);
    }
}

// round 4
// speedup vs baseline: 2.0664x; 1.1105x over previous
#include <cuda_runtime.h>
#include <math.h>
#include <stdint.h>

constexpr int NB    = 32;
constexpr int NKV   = 2048;
constexpr int NHID  = 2560;
constexpr int NHEADS= 32;
constexpr int NHD   = 80;
constexpr int NNI   = 10240;
constexpr int NQKV  = 3 * NHID;
constexpr int ASPLIT= 8;       // attention KV splits
constexpr int ATOK  = 256;     // tokens per attention block

// GEMM tiling
constexpr int GK  = 64;        // k-tile
constexpr int GN  = 128;       // n per block (4 warps x 32)
constexpr int XS_STRIDE = 68;
constexpr int WS_STRIDE = 64;
constexpr int XS_FLOATS = 32 * XS_STRIDE;
constexpr int WS_FLOATS = GN * WS_STRIDE;
constexpr int SMEM_FLOATS = 2 * (XS_FLOATS + WS_FLOATS);
constexpr int SMEM_BYTES  = SMEM_FLOATS * 4;       // 82944

// Scratch (allocation-free: device globals). Per-GEMM partials so the two
// stream tracks never race on scratch.
__device__ __align__(16) float g_x[NB * NHID];
__device__ __align__(16) float g_qkv[NB * NQKV];
__device__ __align__(16) float g_attn[NB * NHID];
__device__ __align__(16) float g_attn_out[NB * NHID];
__device__ __align__(16) float g_hmlp[NB * NNI];
__device__ __align__(16) float g_part_qkv[5  * 32 * NQKV];
__device__ __align__(16) float g_part_out[10 * 32 * NHID];
__device__ __align__(16) float g_part_fc1[4  * 32 * NNI];
__device__ __align__(16) float g_part_fc2[16 * 32 * NHID];
__device__ __align__(16) float g_pm[NB * NHEADS * ASPLIT];
__device__ __align__(16) float g_pl[NB * NHEADS * ASPLIT];
__device__ __align__(16) float g_po[NB * NHEADS * ASPLIT * NHD];

// ---------------------------------------------------------------------------
__device__ __forceinline__ uint32_t f2tf32(float x) {
    uint32_t r;
    asm("cvt.rna.tf32.f32 %0, %1;" : "=r"(r) : "f"(x));
    return r;
}

__device__ __forceinline__ void mma_tf32(float* d, const uint32_t* a,
                                         uint32_t b0, uint32_t b1) {
    asm volatile(
        "mma.sync.aligned.m16n8k8.row.col.f32.tf32.tf32.f32 "
        "{%0,%1,%2,%3}, {%4,%5,%6,%7}, {%8,%9}, {%0,%1,%2,%3};\n"
        : "+f"(d[0]), "+f"(d[1]), "+f"(d[2]), "+f"(d[3])
        : "r"(a[0]), "r"(a[1]), "r"(a[2]), "r"(a[3]), "r"(b0), "r"(b1));
}

__device__ __forceinline__ void cp_async16(void* dst, const void* src) {
    uint32_t s = (uint32_t)__cvta_generic_to_shared(dst);
    asm volatile("cp.async.cg.shared.global [%0], [%1], 16;\n"
                 :: "r"(s), "l"(src));
}

// ---------------------------------------------------------------------------
// LayerNorm: one block per batch row
// ---------------------------------------------------------------------------
__global__ __launch_bounds__(256) void ln_kernel(
    const float* __restrict__ hs, const float* __restrict__ gam,
    const float* __restrict__ bet, float* __restrict__ xout)
{
    int b = blockIdx.x;
    const float* row = hs + b * NHID;
    float s = 0.f, s2 = 0.f;
    for (int i = threadIdx.x; i < NHID / 4; i += blockDim.x) {
        float4 v = reinterpret_cast<const float4*>(row)[i];
        s  += v.x + v.y + v.z + v.w;
        s2 += v.x * v.x + v.y * v.y + v.z * v.z + v.w * v.w;
    }
    __shared__ float rs[256], rs2[256];
    rs[threadIdx.x] = s; rs2[threadIdx.x] = s2;
    __syncthreads();
    for (int o = 128; o > 0; o >>= 1) {
        if (threadIdx.x < o) {
            rs[threadIdx.x]  += rs[threadIdx.x + o];
            rs2[threadIdx.x] += rs2[threadIdx.x + o];
        }
        __syncthreads();
    }
    float mu  = rs[0] / NHID;
    float var = rs2[0] / NHID - mu * mu;
    float inv = rsqrtf(var + 1e-5f);
    for (int i = threadIdx.x; i < NHID; i += blockDim.x) {
        xout[b * NHID + i] = (row[i] - mu) * inv * gam[i] + bet[i];
    }
}

// ---------------------------------------------------------------------------
// tf32 split-K GEMM, cp.async double-buffered (see R3 notes).
// ---------------------------------------------------------------------------
__global__ __launch_bounds__(128) void gemm_tf32_kernel(
    const float* __restrict__ X, const float* __restrict__ W,
    float* __restrict__ part, int N, int K, int Kper)
{
    extern __shared__ float sm[];
    float* XsBuf[2] = { sm, sm + XS_FLOATS };
    float* WsBuf[2] = { sm + 2 * XS_FLOATS, sm + 2 * XS_FLOATS + WS_FLOATS };

    int tid  = threadIdx.x;
    int w    = tid >> 5;
    int lane = tid & 31;
    int g    = lane >> 2;
    int t    = lane & 3;

    int nbase  = blockIdx.x * GN;
    int nwarp  = nbase + w * 32;
    int ks     = blockIdx.y * Kper;
    int ntiles = Kper / GK;

    float d[2][4][4];
#pragma unroll
    for (int m = 0; m < 2; m++)
#pragma unroll
        for (int s = 0; s < 4; s++)
#pragma unroll
            for (int f = 0; f < 4; f++) d[m][s][f] = 0.f;

    auto stageW = [&](int st, int kt) {
        float* ws = WsBuf[st];
#pragma unroll
        for (int i = 0; i < 16; i++) {
            int c   = tid + i * 128;
            int row = c >> 4;
            int cc  = (c & 15) * 4;
            int pc  = cc ^ ((row & 7) << 2);
            cp_async16(ws + row * WS_STRIDE + pc,
                       W + (size_t)(nbase + row) * K + kt + cc);
        }
        asm volatile("cp.async.commit_group;\n");
    };
    float4 xr[4];
    auto loadX = [&](int kt) {
#pragma unroll
        for (int i = 0; i < 4; i++) {
            int c   = tid + i * 128;
            int row = c >> 4;
            int cc  = (c & 15) * 4;
            xr[i] = *reinterpret_cast<const float4*>(X + (size_t)row * K + kt + cc);
        }
    };
    auto storeX = [&](int st) {
        float* xs = XsBuf[st];
#pragma unroll
        for (int i = 0; i < 4; i++) {
            int c   = tid + i * 128;
            int row = c >> 4;
            int cc  = (c & 15) * 4;
            uint4 u;
            u.x = f2tf32(xr[i].x); u.y = f2tf32(xr[i].y);
            u.z = f2tf32(xr[i].z); u.w = f2tf32(xr[i].w);
            *reinterpret_cast<uint4*>(xs + row * XS_STRIDE + cc) = u;
        }
    };

    stageW(0, ks);
    loadX(ks);
    storeX(0);
    asm volatile("cp.async.wait_group 0;\n");
    __syncthreads();

    for (int it = 0; it < ntiles; it++) {
        int cur = it & 1;
        bool more = (it + 1 < ntiles);
        if (more) {
            stageW(cur ^ 1, ks + (it + 1) * GK);
            loadX(ks + (it + 1) * GK);
        }

        const uint32_t* xs = reinterpret_cast<const uint32_t*>(XsBuf[cur]);
        const float*    ws = WsBuf[cur];
        int sw = (g << 2);
#pragma unroll
        for (int k8 = 0; k8 < GK; k8 += 8) {
            uint32_t a0[4], a1[4];
            a0[0] = xs[(g     ) * XS_STRIDE + k8 + t];
            a0[1] = xs[(g +  8) * XS_STRIDE + k8 + t];
            a0[2] = xs[(g     ) * XS_STRIDE + k8 + t + 4];
            a0[3] = xs[(g +  8) * XS_STRIDE + k8 + t + 4];
            a1[0] = xs[(g + 16) * XS_STRIDE + k8 + t];
            a1[1] = xs[(g + 24) * XS_STRIDE + k8 + t];
            a1[2] = xs[(g + 16) * XS_STRIDE + k8 + t + 4];
            a1[3] = xs[(g + 24) * XS_STRIDE + k8 + t + 4];
#pragma unroll
            for (int s = 0; s < 4; s++) {
                int row = w * 32 + s * 8 + g;
                uint32_t b0 = f2tf32(ws[row * WS_STRIDE + ((k8 + t    ) ^ sw)]);
                uint32_t b1 = f2tf32(ws[row * WS_STRIDE + ((k8 + t + 4) ^ sw)]);
                mma_tf32(d[0][s], a0, b0, b1);
                mma_tf32(d[1][s], a1, b0, b1);
            }
        }

        if (more) {
            storeX(cur ^ 1);
            asm volatile("cp.async.wait_group 0;\n");
        }
        __syncthreads();
    }

    float* pbase = part + (size_t)blockIdx.y * 32 * N;
#pragma unroll
    for (int m = 0; m < 2; m++) {
#pragma unroll
        for (int s = 0; s < 4; s++) {
            int col = nwarp + s * 8 + 2 * t;
            int r0  = g + m * 16;
            float2 lo = make_float2(d[m][s][0], d[m][s][1]);
            float2 hi = make_float2(d[m][s][2], d[m][s][3]);
            *reinterpret_cast<float2*>(pbase + (size_t)r0 * N + col)       = lo;
            *reinterpret_cast<float2*>(pbase + (size_t)(r0 + 8) * N + col) = hi;
        }
    }
}

// ---------------------------------------------------------------------------
// split-K reduce + bias + epilogue.
// EPI: 0 = bias only, 1 = gelu(tanh), 2 = += add1 + add2 (final)
// ---------------------------------------------------------------------------
template <int EPI>
__global__ __launch_bounds__(256) void reduce_kernel(
    const float* __restrict__ part, const float* __restrict__ bias,
    float* __restrict__ C, int N, int KS,
    const float* __restrict__ add1, const float* __restrict__ add2)
{
    int id = blockIdx.x * 256 + threadIdx.x;
    if (id >= 32 * N) return;
    int j = id % N;
    float s = 0.f;
    for (int z = 0; z < KS; z++) s += part[(size_t)z * 32 * N + id];
    float val = s + bias[j];
    if (EPI == 1) {
        float u = val;
        float th = tanhf(0.7978845608028654f * (u + 0.044715f * u * u * u));
        val = 0.5f * u * (1.f + th);
    } else if (EPI == 2) {
        val += add1[id] + add2[id];
    }
    C[id] = val;
}

// ---------------------------------------------------------------------------
__global__ __launch_bounds__(512) void rope_kernel(
    const int* __restrict__ ctxl, float* __restrict__ qkv)
{
    int b = blockIdx.x;
    int t = threadIdx.x;
    int h = t >> 4;
    int i = t & 15;
    float pos = (float)ctxl[b];
    float inv_freq = expf(-(float)(2 * i) / 32.0f * 9.210340371976184f);
    float ang = pos * inv_freq;
    float sn, cs;
    sincosf(ang, &sn, &cs);

    float* q = qkv + (size_t)b * NQKV + h * NHD;
    float x1 = q[i], x2 = q[i + 16];
    q[i]      = x1 * cs - x2 * sn;
    q[i + 16] = x2 * cs + x1 * sn;

    float* k = qkv + (size_t)b * NQKV + NHID + h * NHD;
    x1 = k[i]; x2 = k[i + 16];
    k[i]      = x1 * cs - x2 * sn;
    k[i + 16] = x2 * cs + x1 * sn;
}

// ---------------------------------------------------------------------------
// Flash-decode attention, split-KV: one block per (head, batch, split).
// ---------------------------------------------------------------------------
__global__ __launch_bounds__(256, 4) void attn_split_kernel(
    const int* __restrict__ ctxl,
    const float* __restrict__ kc, const float* __restrict__ vc,
    const float* __restrict__ qkv,
    float* __restrict__ pm, float* __restrict__ pl, float* __restrict__ po)
{
    __shared__ float  sP[ATOK];
    __shared__ float4 sQ[20];
    __shared__ float  sRed[256];
    __shared__ float  sAcc[8][80];

    int h = blockIdx.x, b = blockIdx.y, z = blockIdx.z;
    int tid = threadIdx.x;
    int ctx = ctxl[b];
    int L = ctx + 1;
    int s0 = z * ATOK;
    int s1 = min(L, s0 + ATOK);
    int pidx = ((b * NHEADS + h) * ASPLIT + z);

    if (s0 >= L) {
        if (tid == 0) { pm[pidx] = -1e30f; pl[pidx] = 0.f; }
        if (tid < NHD) po[(size_t)pidx * NHD + tid] = 0.f;
        return;
    }

    const float* qp = qkv + (size_t)b * NQKV + h * NHD;
    if (tid < 20) sQ[tid] = reinterpret_cast<const float4*>(qp)[tid];
    __syncthreads();

    const float scale = 0.11180339887498948f;
    const float* knew = qkv + (size_t)b * NQKV + NHID + h * NHD;
    const float* vnew = qkv + (size_t)b * NQKV + 2 * NHID + h * NHD;

    float lmax = -1e30f;
    for (int s = s0 + tid; s < s1; s += 256) {
        const float* kr = (s == ctx)
            ? knew
            : kc + (((size_t)b * NKV + s) * NHEADS + h) * NHD;
        float dsc = 0.f;
#pragma unroll
        for (int i = 0; i < 20; i++) {
            float4 k4 = reinterpret_cast<const float4*>(kr)[i];
            float4 q4 = sQ[i];
            dsc += k4.x * q4.x + k4.y * q4.y + k4.z * q4.z + k4.w * q4.w;
        }
        dsc *= scale;
        sP[s - s0] = dsc;
        lmax = fmaxf(lmax, dsc);
    }
    sRed[tid] = lmax;
    __syncthreads();
    for (int o = 128; o > 0; o >>= 1) {
        if (tid < o) sRed[tid] = fmaxf(sRed[tid], sRed[tid + o]);
        __syncthreads();
    }
    float m = sRed[0];
    __syncthreads();

    float lsum = 0.f;
    for (int s = s0 + tid; s < s1; s += 256) {
        float e = __expf(sP[s - s0] - m);
        sP[s - s0] = e;
        lsum += e;
    }
    sRed[tid] = lsum;
    __syncthreads();
    for (int o = 128; o > 0; o >>= 1) {
        if (tid < o) sRed[tid] += sRed[tid + o];
        __syncthreads();
    }
    float l = sRed[0];
    __syncthreads();

    int w = tid >> 5, lane = tid & 31;
    float a0 = 0.f, a1 = 0.f, a2 = 0.f;
    for (int s = s0 + w; s < s1; s += 8) {
        float p = sP[s - s0];
        const float* vr = (s == ctx)
            ? vnew
            : vc + (((size_t)b * NKV + s) * NHEADS + h) * NHD;
        a0 += p * vr[lane];
        a1 += p * vr[lane + 32];
        if (lane < 16) a2 += p * vr[lane + 64];
    }
    sAcc[w][lane]      = a0;
    sAcc[w][lane + 32] = a1;
    if (lane < 16) sAcc[w][lane + 64] = a2;
    __syncthreads();

    if (tid < NHD) {
        float s = 0.f;
#pragma unroll
        for (int ww = 0; ww < 8; ww++) s += sAcc[ww][tid];
        po[(size_t)pidx * NHD + tid] = s;
    }
    if (tid == 0) { pm[pidx] = m; pl[pidx] = l; }
}

// ---------------------------------------------------------------------------
__global__ __launch_bounds__(128) void attn_combine_kernel(
    const float* __restrict__ pm, const float* __restrict__ pl,
    const float* __restrict__ po, float* __restrict__ attn)
{
    int h = blockIdx.x, b = blockIdx.y;
    int tid = threadIdx.x;
    if (tid >= NHD) return;
    int base = (b * NHEADS + h) * ASPLIT;

    float M = -1e30f;
#pragma unroll
    for (int z = 0; z < ASPLIT; z++) M = fmaxf(M, pm[base + z]);
    float den = 0.f, num = 0.f;
#pragma unroll
    for (int z = 0; z < ASPLIT; z++) {
        float wz = __expf(pm[base + z] - M);
        den += wz * pl[base + z];
        num += wz * po[(size_t)(base + z) * NHD + tid];
    }
    attn[(size_t)b * NHID + h * NHD + tid] = num / den;
}

// ---------------------------------------------------------------------------
extern "C" void kernel_launch(void* const* d_in, const int* in_sizes, int n_in,
                              void* d_out, int out_size)
{
    const float* hs    = (const float*)d_in[0];
    const int*   ctx   = (const int*)  d_in[1];
    const float* kc    = (const float*)d_in[2];
    const float* vc    = (const float*)d_in[3];
    const float* ln_g  = (const float*)d_in[4];
    const float* ln_b  = (const float*)d_in[5];
    const float* w_qkv = (const float*)d_in[6];
    const float* b_qkv = (const float*)d_in[7];
    const float* w_out = (const float*)d_in[8];
    const float* b_out = (const float*)d_in[9];
    const float* w_fc1 = (const float*)d_in[10];
    const float* b_fc1 = (const float*)d_in[11];
    const float* w_fc2 = (const float*)d_in[12];
    const float* b_fc2 = (const float*)d_in[13];
    float* out = (float*)d_out;

    float *px, *pqkv, *pattn, *pao, *ph;
    float *pp_qkv, *pp_out, *pp_fc1, *pp_fc2, *ppm, *ppl, *ppo;
    cudaGetSymbolAddress((void**)&px,     g_x);
    cudaGetSymbolAddress((void**)&pqkv,   g_qkv);
    cudaGetSymbolAddress((void**)&pattn,  g_attn);
    cudaGetSymbolAddress((void**)&pao,    g_attn_out);
    cudaGetSymbolAddress((void**)&ph,     g_hmlp);
    cudaGetSymbolAddress((void**)&pp_qkv, g_part_qkv);
    cudaGetSymbolAddress((void**)&pp_out, g_part_out);
    cudaGetSymbolAddress((void**)&pp_fc1, g_part_fc1);
    cudaGetSymbolAddress((void**)&pp_fc2, g_part_fc2);
    cudaGetSymbolAddress((void**)&ppm,    g_pm);
    cudaGetSymbolAddress((void**)&ppl,    g_pl);
    cudaGetSymbolAddress((void**)&ppo,    g_po);

    cudaFuncSetAttribute(gemm_tf32_kernel,
                         cudaFuncAttributeMaxDynamicSharedMemorySize, SMEM_BYTES);

    // Host-side objects created once (host allocations only; the captured
    // graph is identical on every call).
    static cudaStream_t side = nullptr;
    static cudaEvent_t  ev_fork = nullptr, ev_join = nullptr;
    if (side == nullptr) {
        cudaStreamCreateWithFlags(&side, cudaStreamNonBlocking);
        cudaEventCreateWithFlags(&ev_fork, cudaEventDisableTiming);
        cudaEventCreateWithFlags(&ev_join, cudaEventDisableTiming);
    }
    cudaStream_t main0 = (cudaStream_t)0;

    // 1. LayerNorm (both tracks depend on it)
    ln_kernel<<<NB, 256, 0, main0>>>(hs, ln_g, ln_b, px);

    // Fork side stream for the MLP track
    cudaEventRecord(ev_fork, main0);
    cudaStreamWaitEvent(side, ev_fork, 0);

    // ---- Track B (side): fc1 gemm -> gelu reduce -> fc2 gemm ----
    {
        dim3 gr(NNI / GN, 4);
        gemm_tf32_kernel<<<gr, 128, SMEM_BYTES, side>>>(px, w_fc1, pp_fc1,
                                                        NNI, NHID, 640);
        reduce_kernel<1><<<(32 * NNI + 255) / 256, 256, 0, side>>>(
            pp_fc1, b_fc1, ph, NNI, 4, nullptr, nullptr);
        dim3 gr2(NHID / GN, 16);
        gemm_tf32_kernel<<<gr2, 128, SMEM_BYTES, side>>>(ph, w_fc2, pp_fc2,
                                                         NHID, NNI, 640);
        cudaEventRecord(ev_join, side);
    }

    // ---- Track A (main): qkv -> rope -> attention -> out-proj ----
    {
        dim3 gr(NQKV / GN, 5);
        gemm_tf32_kernel<<<gr, 128, SMEM_BYTES, main0>>>(px, w_qkv, pp_qkv,
                                                         NQKV, NHID, 512);
        reduce_kernel<0><<<(32 * NQKV + 255) / 256, 256, 0, main0>>>(
            pp_qkv, b_qkv, pqkv, NQKV, 5, nullptr, nullptr);

        rope_kernel<<<NB, 512, 0, main0>>>(ctx, pqkv);

        dim3 ag(NHEADS, NB, ASPLIT);
        attn_split_kernel<<<ag, 256, 0, main0>>>(ctx, kc, vc, pqkv,
                                                 ppm, ppl, ppo);
        dim3 cg(NHEADS, NB);
        attn_combine_kernel<<<cg, 128, 0, main0>>>(ppm, ppl, ppo, pattn);

        dim3 gr2(NHID / GN, 10);
        gemm_tf32_kernel<<<gr2, 128, SMEM_BYTES, main0>>>(pattn, w_out, pp_out,
                                                          NHID, NHID, 256);
        reduce_kernel<0><<<(32 * NHID + 255) / 256, 256, 0, main0>>>(
            pp_out, b_out, pao, NHID, 10, nullptr, nullptr);
    }

    // Join and finish: fc2 reduce consumes fc2 partials + attn_out + residual
    cudaStreamWaitEvent(main0, ev_join, 0);
    reduce_kernel<2><<<(32 * NHID + 255) / 256, 256, 0, main0>>>(
        pp_fc2, b_fc2, out, NHID, 16, pao, hs);
}

// round 5
// speedup vs baseline: 2.2494x; 1.0886x over previous
#include <cuda_runtime.h>
#include <math.h>
#include <stdint.h>

constexpr int NB    = 32;
constexpr int NKV   = 2048;
constexpr int NHID  = 2560;
constexpr int NHEADS= 32;
constexpr int NHD   = 80;
constexpr int NNI   = 10240;
constexpr int NQKV  = 3 * NHID;
constexpr int ASPLIT= 8;
constexpr int ATOK  = 256;

// GEMM tiling: block = 256 thr (8 warps), tile 32m x 128n x 64k
constexpr int GK  = 64;
constexpr int GN  = 128;
constexpr int XS_STRIDE = 68;
constexpr int WS_STRIDE = 64;
constexpr int XS_FLOATS = 32 * XS_STRIDE;
constexpr int WS_FLOATS = GN * WS_STRIDE;
constexpr int SMEM_FLOATS = 2 * (XS_FLOATS + WS_FLOATS);
constexpr int SMEM_BYTES  = SMEM_FLOATS * 4;       // 82944

// Scratch (allocation-free: device globals); per-GEMM partials (stream-safe).
__device__ __align__(16) float g_x[NB * NHID];
__device__ __align__(16) float g_qkv[NB * NQKV];
__device__ __align__(16) float g_attn[NB * NHID];
__device__ __align__(16) float g_attn_out[NB * NHID];
__device__ __align__(16) float g_hmlp[NB * NNI];
__device__ __align__(16) float g_part_qkv[5  * 32 * NQKV];
__device__ __align__(16) float g_part_out[10 * 32 * NHID];
__device__ __align__(16) float g_part_fc1[4  * 32 * NNI];
__device__ __align__(16) float g_part_fc2[16 * 32 * NHID];
__device__ __align__(16) float g_pm[NB * NHEADS * ASPLIT];
__device__ __align__(16) float g_pl[NB * NHEADS * ASPLIT];
__device__ __align__(16) float g_po[NB * NHEADS * ASPLIT * NHD];

// ---------------------------------------------------------------------------
__device__ __forceinline__ uint32_t f2tf32(float x) {
    uint32_t r;
    asm("cvt.rna.tf32.f32 %0, %1;" : "=r"(r) : "f"(x));
    return r;
}

__device__ __forceinline__ void mma_tf32(float* d, const uint32_t* a,
                                         uint32_t b0, uint32_t b1) {
    asm volatile(
        "mma.sync.aligned.m16n8k8.row.col.f32.tf32.tf32.f32 "
        "{%0,%1,%2,%3}, {%4,%5,%6,%7}, {%8,%9}, {%0,%1,%2,%3};\n"
        : "+f"(d[0]), "+f"(d[1]), "+f"(d[2]), "+f"(d[3])
        : "r"(a[0]), "r"(a[1]), "r"(a[2]), "r"(a[3]), "r"(b0), "r"(b1));
}

__device__ __forceinline__ void cp_async16(void* dst, const void* src) {
    uint32_t s = (uint32_t)__cvta_generic_to_shared(dst);
    asm volatile("cp.async.cg.shared.global [%0], [%1], 16;\n"
                 :: "r"(s), "l"(src));
}

// ---------------------------------------------------------------------------
__global__ __launch_bounds__(256) void ln_kernel(
    const float* __restrict__ hs, const float* __restrict__ gam,
    const float* __restrict__ bet, float* __restrict__ xout)
{
    int b = blockIdx.x;
    const float* row = hs + b * NHID;
    float s = 0.f, s2 = 0.f;
    for (int i = threadIdx.x; i < NHID / 4; i += blockDim.x) {
        float4 v = reinterpret_cast<const float4*>(row)[i];
        s  += v.x + v.y + v.z + v.w;
        s2 += v.x * v.x + v.y * v.y + v.z * v.z + v.w * v.w;
    }
    __shared__ float rs[256], rs2[256];
    rs[threadIdx.x] = s; rs2[threadIdx.x] = s2;
    __syncthreads();
    for (int o = 128; o > 0; o >>= 1) {
        if (threadIdx.x < o) {
            rs[threadIdx.x]  += rs[threadIdx.x + o];
            rs2[threadIdx.x] += rs2[threadIdx.x + o];
        }
        __syncthreads();
    }
    float mu  = rs[0] / NHID;
    float var = rs2[0] / NHID - mu * mu;
    float inv = rsqrtf(var + 1e-5f);
    for (int i = threadIdx.x; i < NHID; i += blockDim.x) {
        xout[b * NHID + i] = (row[i] - mu) * inv * gam[i] + bet[i];
    }
}

// ---------------------------------------------------------------------------
// tf32 split-K GEMM, cp.async double-buffered. 256 thr = 8 warps.
// Warp w computes 32m x 16n (cols w*16 .. w*16+15 of the 128n block tile).
// ---------------------------------------------------------------------------
__global__ __launch_bounds__(256) void gemm_tf32_kernel(
    const float* __restrict__ X, const float* __restrict__ W,
    float* __restrict__ part, int N, int K, int Kper)
{
    extern __shared__ float sm[];
    float* XsBuf[2] = { sm, sm + XS_FLOATS };
    float* WsBuf[2] = { sm + 2 * XS_FLOATS, sm + 2 * XS_FLOATS + WS_FLOATS };

    int tid  = threadIdx.x;
    int w    = tid >> 5;
    int lane = tid & 31;
    int g    = lane >> 2;
    int t    = lane & 3;

    int nbase  = blockIdx.x * GN;
    int ks     = blockIdx.y * Kper;
    int ntiles = Kper / GK;

    float d[2][2][4];
#pragma unroll
    for (int m = 0; m < 2; m++)
#pragma unroll
        for (int s = 0; s < 2; s++)
#pragma unroll
            for (int f = 0; f < 4; f++) d[m][s][f] = 0.f;

    auto stageW = [&](int st, int kt) {
        float* ws = WsBuf[st];
#pragma unroll
        for (int i = 0; i < 8; i++) {
            int c   = tid + i * 256;      // 0..2047
            int row = c >> 4;
            int cc  = (c & 15) * 4;
            int pc  = cc ^ ((row & 7) << 2);
            cp_async16(ws + row * WS_STRIDE + pc,
                       W + (size_t)(nbase + row) * K + kt + cc);
        }
        asm volatile("cp.async.commit_group;\n");
    };
    float4 xr[2];
    auto loadX = [&](int kt) {
#pragma unroll
        for (int i = 0; i < 2; i++) {
            int c   = tid + i * 256;      // 0..511
            int row = c >> 4;
            int cc  = (c & 15) * 4;
            xr[i] = *reinterpret_cast<const float4*>(X + (size_t)row * K + kt + cc);
        }
    };
    auto storeX = [&](int st) {
        float* xs = XsBuf[st];
#pragma unroll
        for (int i = 0; i < 2; i++) {
            int c   = tid + i * 256;
            int row = c >> 4;
            int cc  = (c & 15) * 4;
            uint4 u;
            u.x = f2tf32(xr[i].x); u.y = f2tf32(xr[i].y);
            u.z = f2tf32(xr[i].z); u.w = f2tf32(xr[i].w);
            *reinterpret_cast<uint4*>(xs + row * XS_STRIDE + cc) = u;
        }
    };

    stageW(0, ks);
    loadX(ks);
    storeX(0);
    asm volatile("cp.async.wait_group 0;\n");
    __syncthreads();

    for (int it = 0; it < ntiles; it++) {
        int cur = it & 1;
        bool more = (it + 1 < ntiles);
        if (more) {
            stageW(cur ^ 1, ks + (it + 1) * GK);
            loadX(ks + (it + 1) * GK);
        }

        const uint32_t* xs = reinterpret_cast<const uint32_t*>(XsBuf[cur]);
        const float*    ws = WsBuf[cur];
        int sw = (g << 2);
#pragma unroll
        for (int k8 = 0; k8 < GK; k8 += 8) {
            uint32_t a0[4], a1[4];
            a0[0] = xs[(g     ) * XS_STRIDE + k8 + t];
            a0[1] = xs[(g +  8) * XS_STRIDE + k8 + t];
            a0[2] = xs[(g     ) * XS_STRIDE + k8 + t + 4];
            a0[3] = xs[(g +  8) * XS_STRIDE + k8 + t + 4];
            a1[0] = xs[(g + 16) * XS_STRIDE + k8 + t];
            a1[1] = xs[(g + 24) * XS_STRIDE + k8 + t];
            a1[2] = xs[(g + 16) * XS_STRIDE + k8 + t + 4];
            a1[3] = xs[(g + 24) * XS_STRIDE + k8 + t + 4];
#pragma unroll
            for (int s = 0; s < 2; s++) {
                int row = w * 16 + s * 8 + g;     // (row & 7) == g
                uint32_t b0 = f2tf32(ws[row * WS_STRIDE + ((k8 + t    ) ^ sw)]);
                uint32_t b1 = f2tf32(ws[row * WS_STRIDE + ((k8 + t + 4) ^ sw)]);
                mma_tf32(d[0][s], a0, b0, b1);
                mma_tf32(d[1][s], a1, b0, b1);
            }
        }

        if (more) {
            storeX(cur ^ 1);
            asm volatile("cp.async.wait_group 0;\n");
        }
        __syncthreads();
    }

    float* pbase = part + (size_t)blockIdx.y * 32 * N;
#pragma unroll
    for (int m = 0; m < 2; m++) {
#pragma unroll
        for (int s = 0; s < 2; s++) {
            int col = nbase + w * 16 + s * 8 + 2 * t;
            int r0  = g + m * 16;
            float2 lo = make_float2(d[m][s][0], d[m][s][1]);
            float2 hi = make_float2(d[m][s][2], d[m][s][3]);
            *reinterpret_cast<float2*>(pbase + (size_t)r0 * N + col)       = lo;
            *reinterpret_cast<float2*>(pbase + (size_t)(r0 + 8) * N + col) = hi;
        }
    }
}

// ---------------------------------------------------------------------------
template <int EPI>
__global__ __launch_bounds__(256) void reduce_kernel(
    const float* __restrict__ part, const float* __restrict__ bias,
    float* __restrict__ C, int N, int KS,
    const float* __restrict__ add1, const float* __restrict__ add2)
{
    int id = blockIdx.x * 256 + threadIdx.x;
    if (id >= 32 * N) return;
    int j = id % N;
    float s = 0.f;
    for (int z = 0; z < KS; z++) s += part[(size_t)z * 32 * N + id];
    float val = s + bias[j];
    if (EPI == 1) {
        float u = val;
        float th = tanhf(0.7978845608028654f * (u + 0.044715f * u * u * u));
        val = 0.5f * u * (1.f + th);
    } else if (EPI == 2) {
        val += add1[id] + add2[id];
    }
    C[id] = val;
}

// ---------------------------------------------------------------------------
__global__ __launch_bounds__(512) void rope_kernel(
    const int* __restrict__ ctxl, float* __restrict__ qkv)
{
    int b = blockIdx.x;
    int t = threadIdx.x;
    int h = t >> 4;
    int i = t & 15;
    float pos = (float)ctxl[b];
    float inv_freq = expf(-(float)(2 * i) / 32.0f * 9.210340371976184f);
    float ang = pos * inv_freq;
    float sn, cs;
    sincosf(ang, &sn, &cs);

    float* q = qkv + (size_t)b * NQKV + h * NHD;
    float x1 = q[i], x2 = q[i + 16];
    q[i]      = x1 * cs - x2 * sn;
    q[i + 16] = x2 * cs + x1 * sn;

    float* k = qkv + (size_t)b * NQKV + NHID + h * NHD;
    x1 = k[i]; x2 = k[i + 16];
    k[i]      = x1 * cs - x2 * sn;
    k[i + 16] = x2 * cs + x1 * sn;
}

// ---------------------------------------------------------------------------
// Flash-decode attention, split-KV. Pass 1 is warp-per-row (coalesced K reads).
// ---------------------------------------------------------------------------
__global__ __launch_bounds__(256, 4) void attn_split_kernel(
    const int* __restrict__ ctxl,
    const float* __restrict__ kc, const float* __restrict__ vc,
    const float* __restrict__ qkv,
    float* __restrict__ pm, float* __restrict__ pl, float* __restrict__ po)
{
    __shared__ float  sP[ATOK];
    __shared__ float4 sQ[20];
    __shared__ float  sRed[256];
    __shared__ float  sAcc[8][80];

    int h = blockIdx.x, b = blockIdx.y, z = blockIdx.z;
    int tid = threadIdx.x;
    int w = tid >> 5, lane = tid & 31;
    int ctx = ctxl[b];
    int L = ctx + 1;
    int s0 = z * ATOK;
    int s1 = min(L, s0 + ATOK);
    int cnt = s1 - s0;
    int pidx = ((b * NHEADS + h) * ASPLIT + z);

    if (s0 >= L) {
        if (tid == 0) { pm[pidx] = -1e30f; pl[pidx] = 0.f; }
        if (tid < NHD) po[(size_t)pidx * NHD + tid] = 0.f;
        return;
    }

    const float* qp = qkv + (size_t)b * NQKV + h * NHD;
    if (tid < 20) sQ[tid] = reinterpret_cast<const float4*>(qp)[tid];
    __syncthreads();

    const float scale = 0.11180339887498948f; // 80^-0.5
    const float* knew = qkv + (size_t)b * NQKV + NHID + h * NHD;
    const float* vnew = qkv + (size_t)b * NQKV + 2 * NHID + h * NHD;

    // Pass 1: warp per row; lanes 0..19 load float4 of K row (coalesced).
    float4 q4 = (lane < 20) ? sQ[lane] : make_float4(0.f, 0.f, 0.f, 0.f);
#pragma unroll 2
    for (int s = s0 + w; s < s1; s += 8) {
        const float* kr = (s == ctx)
            ? knew
            : kc + (((size_t)b * NKV + s) * NHEADS + h) * NHD;
        float part = 0.f;
        if (lane < 20) {
            float4 k4 = reinterpret_cast<const float4*>(kr)[lane];
            part = k4.x * q4.x + k4.y * q4.y + k4.z * q4.z + k4.w * q4.w;
        }
#pragma unroll
        for (int o = 16; o > 0; o >>= 1)
            part += __shfl_xor_sync(0xffffffffu, part, o);
        if (lane == 0) sP[s - s0] = part * scale;
    }
    __syncthreads();

    // Block softmax over sP[0..cnt)
    float myv = (tid < cnt) ? sP[tid] : -1e30f;
    sRed[tid] = myv;
    __syncthreads();
    for (int o = 128; o > 0; o >>= 1) {
        if (tid < o) sRed[tid] = fmaxf(sRed[tid], sRed[tid + o]);
        __syncthreads();
    }
    float m = sRed[0];
    __syncthreads();

    float e = (tid < cnt) ? __expf(myv - m) : 0.f;
    if (tid < cnt) sP[tid] = e;
    sRed[tid] = e;
    __syncthreads();
    for (int o = 128; o > 0; o >>= 1) {
        if (tid < o) sRed[tid] += sRed[tid + o];
        __syncthreads();
    }
    float l = sRed[0];
    __syncthreads();

    // Pass 2: weighted V (unnormalized), warps split s (already coalesced)
    float a0 = 0.f, a1 = 0.f, a2 = 0.f;
    for (int s = s0 + w; s < s1; s += 8) {
        float p = sP[s - s0];
        const float* vr = (s == ctx)
            ? vnew
            : vc + (((size_t)b * NKV + s) * NHEADS + h) * NHD;
        a0 += p * vr[lane];
        a1 += p * vr[lane + 32];
        if (lane < 16) a2 += p * vr[lane + 64];
    }
    sAcc[w][lane]      = a0;
    sAcc[w][lane + 32] = a1;
    if (lane < 16) sAcc[w][lane + 64] = a2;
    __syncthreads();

    if (tid < NHD) {
        float s = 0.f;
#pragma unroll
        for (int ww = 0; ww < 8; ww++) s += sAcc[ww][tid];
        po[(size_t)pidx * NHD + tid] = s;
    }
    if (tid == 0) { pm[pidx] = m; pl[pidx] = l; }
}

// ---------------------------------------------------------------------------
__global__ __launch_bounds__(128) void attn_combine_kernel(
    const float* __restrict__ pm, const float* __restrict__ pl,
    const float* __restrict__ po, float* __restrict__ attn)
{
    int h = blockIdx.x, b = blockIdx.y;
    int tid = threadIdx.x;
    if (tid >= NHD) return;
    int base = (b * NHEADS + h) * ASPLIT;

    float M = -1e30f;
#pragma unroll
    for (int z = 0; z < ASPLIT; z++) M = fmaxf(M, pm[base + z]);
    float den = 0.f, num = 0.f;
#pragma unroll
    for (int z = 0; z < ASPLIT; z++) {
        float wz = __expf(pm[base + z] - M);
        den += wz * pl[base + z];
        num += wz * po[(size_t)(base + z) * NHD + tid];
    }
    attn[(size_t)b * NHID + h * NHD + tid] = num / den;
}

// ---------------------------------------------------------------------------
extern "C" void kernel_launch(void* const* d_in, const int* in_sizes, int n_in,
                              void* d_out, int out_size)
{
    const float* hs    = (const float*)d_in[0];
    const int*   ctx   = (const int*)  d_in[1];
    const float* kc    = (const float*)d_in[2];
    const float* vc    = (const float*)d_in[3];
    const float* ln_g  = (const float*)d_in[4];
    const float* ln_b  = (const float*)d_in[5];
    const float* w_qkv = (const float*)d_in[6];
    const float* b_qkv = (const float*)d_in[7];
    const float* w_out = (const float*)d_in[8];
    const float* b_out = (const float*)d_in[9];
    const float* w_fc1 = (const float*)d_in[10];
    const float* b_fc1 = (const float*)d_in[11];
    const float* w_fc2 = (const float*)d_in[12];
    const float* b_fc2 = (const float*)d_in[13];
    float* out = (float*)d_out;

    float *px, *pqkv, *pattn, *pao, *ph;
    float *pp_qkv, *pp_out, *pp_fc1, *pp_fc2, *ppm, *ppl, *ppo;
    cudaGetSymbolAddress((void**)&px,     g_x);
    cudaGetSymbolAddress((void**)&pqkv,   g_qkv);
    cudaGetSymbolAddress((void**)&pattn,  g_attn);
    cudaGetSymbolAddress((void**)&pao,    g_attn_out);
    cudaGetSymbolAddress((void**)&ph,     g_hmlp);
    cudaGetSymbolAddress((void**)&pp_qkv, g_part_qkv);
    cudaGetSymbolAddress((void**)&pp_out, g_part_out);
    cudaGetSymbolAddress((void**)&pp_fc1, g_part_fc1);
    cudaGetSymbolAddress((void**)&pp_fc2, g_part_fc2);
    cudaGetSymbolAddress((void**)&ppm,    g_pm);
    cudaGetSymbolAddress((void**)&ppl,    g_pl);
    cudaGetSymbolAddress((void**)&ppo,    g_po);

    cudaFuncSetAttribute(gemm_tf32_kernel,
                         cudaFuncAttributeMaxDynamicSharedMemorySize, SMEM_BYTES);

    static cudaStream_t side = nullptr;
    static cudaEvent_t  ev_fork = nullptr, ev_join = nullptr;
    if (side == nullptr) {
        cudaStreamCreateWithFlags(&side, cudaStreamNonBlocking);
        cudaEventCreateWithFlags(&ev_fork, cudaEventDisableTiming);
        cudaEventCreateWithFlags(&ev_join, cudaEventDisableTiming);
    }
    cudaStream_t main0 = (cudaStream_t)0;

    // 1. LayerNorm
    ln_kernel<<<NB, 256, 0, main0>>>(hs, ln_g, ln_b, px);

    cudaEventRecord(ev_fork, main0);
    cudaStreamWaitEvent(side, ev_fork, 0);

    // ---- Track B (side): fc1 -> gelu -> fc2 ----
    {
        dim3 gr(NNI / GN, 4);
        gemm_tf32_kernel<<<gr, 256, SMEM_BYTES, side>>>(px, w_fc1, pp_fc1,
                                                        NNI, NHID, 640);
        reduce_kernel<1><<<(32 * NNI + 255) / 256, 256, 0, side>>>(
            pp_fc1, b_fc1, ph, NNI, 4, nullptr, nullptr);
        dim3 gr2(NHID / GN, 16);
        gemm_tf32_kernel<<<gr2, 256, SMEM_BYTES, side>>>(ph, w_fc2, pp_fc2,
                                                         NHID, NNI, 640);
        cudaEventRecord(ev_join, side);
    }

    // ---- Track A (main): qkv -> rope -> attention -> out-proj ----
    {
        dim3 gr(NQKV / GN, 5);
        gemm_tf32_kernel<<<gr, 256, SMEM_BYTES, main0>>>(px, w_qkv, pp_qkv,
                                                         NQKV, NHID, 512);
        reduce_kernel<0><<<(32 * NQKV + 255) / 256, 256, 0, main0>>>(
            pp_qkv, b_qkv, pqkv, NQKV, 5, nullptr, nullptr);

        rope_kernel<<<NB, 512, 0, main0>>>(ctx, pqkv);

        dim3 ag(NHEADS, NB, ASPLIT);
        attn_split_kernel<<<ag, 256, 0, main0>>>(ctx, kc, vc, pqkv,
                                                 ppm, ppl, ppo);
        dim3 cg(NHEADS, NB);
        attn_combine_kernel<<<cg, 128, 0, main0>>>(ppm, ppl, ppo, pattn);

        dim3 gr2(NHID / GN, 10);
        gemm_tf32_kernel<<<gr2, 256, SMEM_BYTES, main0>>>(pattn, w_out, pp_out,
                                                          NHID, NHID, 256);
        reduce_kernel<0><<<(32 * NHID + 255) / 256, 256, 0, main0>>>(
            pp_out, b_out, pao, NHID, 10, nullptr, nullptr);
    }

    cudaStreamWaitEvent(main0, ev_join, 0);
    reduce_kernel<2><<<(32 * NHID + 255) / 256, 256, 0, main0>>>(
        pp_fc2, b_fc2, out, NHID, 16, pao, hs);
}